// round 1
// baseline (speedup 1.0000x reference)
#include <cuda_runtime.h>
#include <cstdint>

// ---------------------------------------------------------------------------
// HypergraphAttentionLayer
//   h   = x @ W^T                         (N=200000, F_IN=128, F_OUT=64)
//   s1  = h @ a[:64], s2 = h @ a[64:]     (fused into GEMM epilogue)
//   edge_attention[e] = sum_r s1[n_er]*(31-r) + s2[n_er]*r, /496
// Output layout: d_out[0 .. N*64)   = h (row-major fp32)
//                d_out[N*64 .. +H)  = edge_attention
// ---------------------------------------------------------------------------

#define F_IN  128
#define F_OUT 64
#define DEG   32
#define NPAIRS 496.0f
#define MAX_N 200704   // scratch capacity (>= N)

// scratch for (s1, s2) per node — static __device__ (no allocation allowed)
__device__ float2 g_s12[MAX_N];

// packed f32x2 FMA (Blackwell FFMA2 — 2x fp32 throughput, PTX-only)
__device__ __forceinline__ void ffma2(unsigned long long& d,
                                      unsigned long long a,
                                      unsigned long long b) {
    asm("fma.rn.f32x2 %0, %1, %2, %0;" : "+l"(d) : "l"(a), "l"(b));
}
__device__ __forceinline__ unsigned long long pack2(float lo, float hi) {
    unsigned long long r;
    asm("mov.b64 %0, {%1, %2};" : "=l"(r) : "f"(lo), "f"(hi));
    return r;
}
__device__ __forceinline__ float2 unpack2(unsigned long long v) {
    float2 r;
    asm("mov.b64 {%0, %1}, %2;" : "=f"(r.x), "=f"(r.y) : "l"(v));
    return r;
}

// ---------------------------------------------------------------------------
// Kernel 1: fused GEMM + score projection.
// One thread = one row of x. W^T staged in shared (k-major: Wt[k][o]),
// broadcast LDS.128, packed FFMA2 accumulators (32 x f32x2 = 64 outputs).
// ---------------------------------------------------------------------------
__global__ __launch_bounds__(128)
void gemm_score_kernel(const float* __restrict__ x,
                       const float* __restrict__ W,
                       const float* __restrict__ a,
                       float* __restrict__ h_out,
                       int N)
{
    __shared__ float Wt[F_IN * F_OUT];   // 32 KB, Wt[k*64 + o] = W[o*128 + k]
    __shared__ float As[2 * F_OUT];      // attention vector

    // cooperative transpose of W into shared
    for (int idx = threadIdx.x; idx < F_IN * F_OUT; idx += blockDim.x) {
        int k = idx >> 6;          // / 64
        int o = idx & 63;          // % 64
        Wt[idx] = W[o * F_IN + k];
    }
    for (int idx = threadIdx.x; idx < 2 * F_OUT; idx += blockDim.x)
        As[idx] = a[idx];
    __syncthreads();

    int row = blockIdx.x * blockDim.x + threadIdx.x;
    if (row >= N) return;

    unsigned long long acc[F_OUT / 2];
    #pragma unroll
    for (int i = 0; i < F_OUT / 2; ++i) acc[i] = 0ull;  // (0.0f, 0.0f)

    const float4* xr = reinterpret_cast<const float4*>(x + (size_t)row * F_IN);

    #pragma unroll 2
    for (int kk = 0; kk < F_IN / 4; ++kk) {
        float4 xv = xr[kk];
        float xs[4] = {xv.x, xv.y, xv.z, xv.w};
        #pragma unroll
        for (int j = 0; j < 4; ++j) {
            int k = kk * 4 + j;
            unsigned long long xb = pack2(xs[j], xs[j]);
            const ulonglong2* wrow =
                reinterpret_cast<const ulonglong2*>(Wt + k * F_OUT);
            #pragma unroll
            for (int o = 0; o < F_OUT / 4; ++o) {   // 16 x LDS.128
                ulonglong2 w = wrow[o];
                ffma2(acc[2 * o + 0], xb, w.x);
                ffma2(acc[2 * o + 1], xb, w.y);
            }
        }
    }

    // epilogue: write h, fold s1/s2
    float s1 = 0.0f, s2 = 0.0f;
    float4* hout = reinterpret_cast<float4*>(h_out + (size_t)row * F_OUT);
    #pragma unroll
    for (int o = 0; o < F_OUT / 4; ++o) {
        float2 v0 = unpack2(acc[2 * o + 0]);
        float2 v1 = unpack2(acc[2 * o + 1]);
        float4 hv = make_float4(v0.x, v0.y, v1.x, v1.y);
        hout[o] = hv;
        int ob = o * 4;
        s1 = fmaf(hv.x, As[ob + 0], s1);
        s1 = fmaf(hv.y, As[ob + 1], s1);
        s1 = fmaf(hv.z, As[ob + 2], s1);
        s1 = fmaf(hv.w, As[ob + 3], s1);
        s2 = fmaf(hv.x, As[F_OUT + ob + 0], s2);
        s2 = fmaf(hv.y, As[F_OUT + ob + 1], s2);
        s2 = fmaf(hv.z, As[F_OUT + ob + 2], s2);
        s2 = fmaf(hv.w, As[F_OUT + ob + 3], s2);
    }
    g_s12[row] = make_float2(s1, s2);
}

// ---------------------------------------------------------------------------
// Kernel 2: per-hyperedge attention. One warp per edge (DEG = 32, edges are
// repeat(arange(H), 32) so edge e owns incidences [e*32, e*32+32)).
// ---------------------------------------------------------------------------
__global__ __launch_bounds__(256)
void edge_attn_kernel(const int* __restrict__ nodes,
                      float* __restrict__ ea_out,
                      int H)
{
    int gtid = blockIdx.x * blockDim.x + threadIdx.x;
    int e    = gtid >> 5;
    int lane = gtid & 31;
    if (e >= H) return;

    int node = nodes[e * DEG + lane];
    float2 s = g_s12[node];
    float v = s.x * (float)(DEG - 1 - lane) + s.y * (float)lane;

    #pragma unroll
    for (int off = 16; off > 0; off >>= 1)
        v += __shfl_xor_sync(0xFFFFFFFFu, v, off);

    if (lane == 0)
        ea_out[e] = v * (1.0f / NPAIRS);
}

// ---------------------------------------------------------------------------
// launch
// ---------------------------------------------------------------------------
extern "C" void kernel_launch(void* const* d_in, const int* in_sizes, int n_in,
                              void* d_out, int out_size)
{
    const float* x   = (const float*)d_in[0];
    const float* W   = (const float*)d_in[1];
    const float* a   = (const float*)d_in[2];
    const int*   hidx = (const int*)d_in[3];

    int N = in_sizes[0] / F_IN;        // 200000
    int E = in_sizes[3] / 2;           // 1.6M
    int H = E / DEG;                   // 50000

    float* h_out  = (float*)d_out;
    float* ea_out = (float*)d_out + (size_t)N * F_OUT;

    const int* nodes = hidx;           // row 0 of hyperedge_index

    {
        int threads = 128;
        int blocks  = (N + threads - 1) / threads;
        gemm_score_kernel<<<blocks, threads>>>(x, W, a, h_out, N);
    }
    {
        int threads = 256;
        int total   = H * DEG;
        int blocks  = (total + threads - 1) / threads;
        edge_attn_kernel<<<blocks, threads>>>(nodes, ea_out, H);
    }
}

// round 3
// speedup vs baseline: 2.6910x; 2.6910x over previous
#include <cuda_runtime.h>
#include <cuda_bf16.h>
#include <cstdint>

// ---------------------------------------------------------------------------
// HypergraphAttentionLayer on GB300 (sm_103a), portable-PTX tensor path.
// NOTE: harness lowers via compute_103 (no 'a') => tcgen05 is unavailable.
// Use mma.sync m16n8k16 bf16 (HMMA, valid sm_80+) with split-bf16:
//   h ~= x_hi*W_hi + x_hi*W_lo + x_lo*W_hi     (error ~2^-16, tol 1e-3)
// s1 = h@a[:64], s2 = h@a[64:] fused in epilogue.
// ea[e] = (sum_r s1*(31-r) + s2*r) / 496
// ---------------------------------------------------------------------------

#define F_IN   128
#define F_OUT  64
#define DEG    32
#define NPAIRS 496.0f
#define MAX_N  200704
#define TILE_M 128
#define PITCH  136      // bf16 elems per smem row (128 + 8 pad -> conflict-free)
#define PITCHW 68       // 32-bit words per smem row

__device__ float2 g_s12[MAX_N];

// smem byte offsets
#define SM_AVEC 0
#define SM_A_HI 512
#define SM_A_LO (SM_A_HI + TILE_M * PITCH * 2)   // +34816
#define SM_B_HI (SM_A_LO + TILE_M * PITCH * 2)
#define SM_B_LO (SM_B_HI + F_OUT * PITCH * 2)    // +17408
#define SM_TOTAL (SM_B_LO + F_OUT * PITCH * 2)   // 104960 B

__device__ __forceinline__ void mma_bf16(float c[4],
                                         uint32_t a0, uint32_t a1,
                                         uint32_t a2, uint32_t a3,
                                         uint32_t b0, uint32_t b1)
{
    asm volatile(
        "mma.sync.aligned.m16n8k16.row.col.f32.bf16.bf16.f32 "
        "{%0,%1,%2,%3}, {%4,%5,%6,%7}, {%8,%9}, {%0,%1,%2,%3};"
        : "+f"(c[0]), "+f"(c[1]), "+f"(c[2]), "+f"(c[3])
        : "r"(a0), "r"(a1), "r"(a2), "r"(a3), "r"(b0), "r"(b1));
}

__device__ __forceinline__ void split_pack(float4 v, uint2& hi, uint2& lo) {
    float f[4] = {v.x, v.y, v.z, v.w};
    __nv_bfloat16 h[4], l[4];
#pragma unroll
    for (int j = 0; j < 4; ++j) {
        h[j] = __float2bfloat16_rn(f[j]);
        l[j] = __float2bfloat16_rn(f[j] - __bfloat162float(h[j]));
    }
    __nv_bfloat162 h01 = __halves2bfloat162(h[0], h[1]);
    __nv_bfloat162 h23 = __halves2bfloat162(h[2], h[3]);
    __nv_bfloat162 l01 = __halves2bfloat162(l[0], l[1]);
    __nv_bfloat162 l23 = __halves2bfloat162(l[2], l[3]);
    hi.x = *reinterpret_cast<uint32_t*>(&h01);
    hi.y = *reinterpret_cast<uint32_t*>(&h23);
    lo.x = *reinterpret_cast<uint32_t*>(&l01);
    lo.y = *reinterpret_cast<uint32_t*>(&l23);
}

// ---------------------------------------------------------------------------
// Kernel 1: HMMA GEMM tile (128 x 64 x K128, 3 bf16 chains) + fused s1/s2.
// 4 warps; warp w owns rows [w*32, w*32+32): 2 m16 frags x 8 n8 frags.
// ---------------------------------------------------------------------------
__global__ __launch_bounds__(128)
void gemm_hmma_kernel(const float* __restrict__ x,
                      const float* __restrict__ W,
                      const float* __restrict__ a,
                      float* __restrict__ h_out,
                      int N)
{
    extern __shared__ char smem[];
    float*    As = reinterpret_cast<float*>(smem + SM_AVEC);
    uint32_t* Ah = reinterpret_cast<uint32_t*>(smem + SM_A_HI);
    uint32_t* Al = reinterpret_cast<uint32_t*>(smem + SM_A_LO);
    uint32_t* Bh = reinterpret_cast<uint32_t*>(smem + SM_B_HI);
    uint32_t* Bl = reinterpret_cast<uint32_t*>(smem + SM_B_LO);

    const int tid  = threadIdx.x;
    const int wid  = tid >> 5;
    const int lane = tid & 31;
    const int row0 = blockIdx.x * TILE_M;

    if (tid < 2 * F_OUT) As[tid] = a[tid];

    // ---- W (64 x 128 fp32) -> B_hi/B_lo bf16, coalesced float4 ----
#pragma unroll
    for (int it = 0; it < 16; ++it) {
        int idx = it * 128 + tid;      // 2048 float4 total
        int n   = idx >> 5;
        int c4  = idx & 31;
        float4 v = reinterpret_cast<const float4*>(W)[n * 32 + c4];
        uint2 hi, lo;
        split_pack(v, hi, lo);
        int w = n * PITCHW + c4 * 2;
        *reinterpret_cast<uint2*>(Bh + w) = hi;
        *reinterpret_cast<uint2*>(Bl + w) = lo;
    }

    // ---- x tile (128 x 128 fp32) -> A_hi/A_lo bf16, coalesced ----
#pragma unroll
    for (int it = 0; it < 32; ++it) {
        int idx = it * 128 + tid;      // 4096 float4 total
        int r   = idx >> 5;
        int c4  = idx & 31;
        int rg  = row0 + r;
        float4 v = (rg < N)
            ? reinterpret_cast<const float4*>(x)[(size_t)rg * 32 + c4]
            : make_float4(0.f, 0.f, 0.f, 0.f);
        uint2 hi, lo;
        split_pack(v, hi, lo);
        int w = r * PITCHW + c4 * 2;
        *reinterpret_cast<uint2*>(Ah + w) = hi;
        *reinterpret_cast<uint2*>(Al + w) = lo;
    }
    __syncthreads();

    const int qr = lane >> 2;          // 0..7
    const int qc = lane & 3;           // 0..3
    const int rb = wid * 32;           // warp row base within tile

    float c[2][8][4];
#pragma unroll
    for (int m = 0; m < 2; ++m)
#pragma unroll
        for (int j = 0; j < 8; ++j)
#pragma unroll
            for (int q = 0; q < 4; ++q) c[m][j][q] = 0.f;

    // ---- K loop: 8 steps of k16, 3 chains merged per step ----
#pragma unroll
    for (int kk = 0; kk < 8; ++kk) {
        int kw = kk * 8 + qc;          // word offset within row for this frag
        uint32_t ah[2][4], al[2][4];
#pragma unroll
        for (int m = 0; m < 2; ++m) {
            int base = (rb + m * 16 + qr) * PITCHW + kw;
            ah[m][0] = Ah[base];
            ah[m][1] = Ah[base + 8 * PITCHW];
            ah[m][2] = Ah[base + 4];
            ah[m][3] = Ah[base + 8 * PITCHW + 4];
            al[m][0] = Al[base];
            al[m][1] = Al[base + 8 * PITCHW];
            al[m][2] = Al[base + 4];
            al[m][3] = Al[base + 8 * PITCHW + 4];
        }
#pragma unroll
        for (int j = 0; j < 8; ++j) {
            int bbase = (j * 8 + qr) * PITCHW + kw;
            uint32_t bh0 = Bh[bbase], bh1 = Bh[bbase + 4];
            uint32_t bl0 = Bl[bbase], bl1 = Bl[bbase + 4];
            // hi*hi
            mma_bf16(c[0][j], ah[0][0], ah[0][1], ah[0][2], ah[0][3], bh0, bh1);
            mma_bf16(c[1][j], ah[1][0], ah[1][1], ah[1][2], ah[1][3], bh0, bh1);
            // lo*hi
            mma_bf16(c[0][j], al[0][0], al[0][1], al[0][2], al[0][3], bh0, bh1);
            mma_bf16(c[1][j], al[1][0], al[1][1], al[1][2], al[1][3], bh0, bh1);
            // hi*lo
            mma_bf16(c[0][j], ah[0][0], ah[0][1], ah[0][2], ah[0][3], bl0, bl1);
            mma_bf16(c[1][j], ah[1][0], ah[1][1], ah[1][2], ah[1][3], bl0, bl1);
        }
    }

    // ---- epilogue: write h (float2 per frag-row), fold s1/s2 ----
#pragma unroll
    for (int m = 0; m < 2; ++m) {
        float s1a = 0.f, s2a = 0.f, s1b = 0.f, s2b = 0.f;
        int ra  = row0 + rb + m * 16 + qr;
        int rbw = ra + 8;
#pragma unroll
        for (int j = 0; j < 8; ++j) {
            int n = j * 8 + qc * 2;
            float a1v = As[n],         a2v = As[n + 1];
            float b1v = As[F_OUT + n], b2v = As[F_OUT + n + 1];
            float* cc = c[m][j];
            if (ra < N)
                *reinterpret_cast<float2*>(h_out + (size_t)ra * F_OUT + n) =
                    make_float2(cc[0], cc[1]);
            if (rbw < N)
                *reinterpret_cast<float2*>(h_out + (size_t)rbw * F_OUT + n) =
                    make_float2(cc[2], cc[3]);
            s1a = fmaf(cc[0], a1v, fmaf(cc[1], a2v, s1a));
            s2a = fmaf(cc[0], b1v, fmaf(cc[1], b2v, s2a));
            s1b = fmaf(cc[2], a1v, fmaf(cc[3], a2v, s1b));
            s2b = fmaf(cc[2], b1v, fmaf(cc[3], b2v, s2b));
        }
#pragma unroll
        for (int off = 1; off <= 2; off <<= 1) {
            s1a += __shfl_xor_sync(0xFFFFFFFFu, s1a, off);
            s2a += __shfl_xor_sync(0xFFFFFFFFu, s2a, off);
            s1b += __shfl_xor_sync(0xFFFFFFFFu, s1b, off);
            s2b += __shfl_xor_sync(0xFFFFFFFFu, s2b, off);
        }
        if (qc == 0) {
            if (ra  < N) g_s12[ra]  = make_float2(s1a, s2a);
            if (rbw < N) g_s12[rbw] = make_float2(s1b, s2b);
        }
    }
}

// ---------------------------------------------------------------------------
// Kernel 2: per-hyperedge attention (one warp per edge, DEG == 32).
// ---------------------------------------------------------------------------
__global__ __launch_bounds__(256)
void edge_attn_kernel(const int* __restrict__ nodes,
                      float* __restrict__ ea_out,
                      int H)
{
    int gtid = blockIdx.x * blockDim.x + threadIdx.x;
    int e    = gtid >> 5;
    int lane = gtid & 31;
    if (e >= H) return;

    int node = nodes[e * DEG + lane];
    float2 s = g_s12[node];
    float v = s.x * (float)(DEG - 1 - lane) + s.y * (float)lane;

#pragma unroll
    for (int off = 16; off > 0; off >>= 1)
        v += __shfl_xor_sync(0xFFFFFFFFu, v, off);

    if (lane == 0)
        ea_out[e] = v * (1.0f / NPAIRS);
}

// ---------------------------------------------------------------------------
extern "C" void kernel_launch(void* const* d_in, const int* in_sizes, int n_in,
                              void* d_out, int out_size)
{
    const float* x    = (const float*)d_in[0];
    const float* W    = (const float*)d_in[1];
    const float* a    = (const float*)d_in[2];
    const int*   hidx = (const int*)d_in[3];

    int N = in_sizes[0] / F_IN;    // 200000
    int E = in_sizes[3] / 2;       // 1,600,000
    int H = E / DEG;               // 50000

    float* h_out  = (float*)d_out;
    float* ea_out = (float*)d_out + (size_t)N * F_OUT;
    const int* nodes = hidx;       // row 0 of hyperedge_index

    cudaFuncSetAttribute(gemm_hmma_kernel,
                         cudaFuncAttributeMaxDynamicSharedMemorySize, SM_TOTAL);

    {
        int blocks = (N + TILE_M - 1) / TILE_M;   // 1563
        gemm_hmma_kernel<<<blocks, 128, SM_TOTAL>>>(x, W, a, h_out, N);
    }
    {
        int total  = H * DEG;
        int blocks = (total + 255) / 256;
        edge_attn_kernel<<<blocks, 256>>>(nodes, ea_out, H);
    }
}

// round 4
// speedup vs baseline: 3.2511x; 1.2081x over previous
#include <cuda_runtime.h>
#include <cuda_bf16.h>
#include <cstdint>

// ---------------------------------------------------------------------------
// HypergraphAttentionLayer on GB300 (sm_103a), portable-PTX tensor path.
// (harness lowers via compute_103 -> no tcgen05; use mma.sync bf16 HMMA)
//   h ~= x_hi*W_hi + x_hi*W_lo + x_lo*W_hi   (split-bf16, err ~2^-16)
//   s1/s2 fused in epilogue; ea[e] = (sum_r s1*(31-r)+s2*r)/496
// Persistent pipelined GEMM: cp.async prefetch of next x tile overlaps MMA.
// ---------------------------------------------------------------------------

#define F_IN   128
#define F_OUT  64
#define DEG    32
#define NPAIRS 496.0f
#define MAX_N  200704
#define TILE_M 128
#define PITCHW 68       // 32-bit words per smem row (64 + 4 pad)

__device__ float2 g_s12[MAX_N];

// smem byte offsets
#define SM_AVEC 0                       // 512 B
#define SM_B_HI 512                     // 64*68*4  = 17408
#define SM_B_LO (SM_B_HI + 17408)
#define SM_A_HI (SM_B_LO + 17408)       // 128*68*4 = 34816
#define SM_A_LO (SM_A_HI + 34816)
#define SM_XRAW (SM_A_LO + 34816)       // 128*128*4 = 65536
#define SM_TOTAL (SM_XRAW + 65536)      // 170496 B

__device__ __forceinline__ uint32_t smem_u32(const void* p) {
    uint32_t a;
    asm("{ .reg .u64 t; cvta.to.shared.u64 t, %1; cvt.u32.u64 %0, t; }"
        : "=r"(a) : "l"(p));
    return a;
}

__device__ __forceinline__ void mma_bf16(float c[4],
                                         uint32_t a0, uint32_t a1,
                                         uint32_t a2, uint32_t a3,
                                         uint32_t b0, uint32_t b1)
{
    asm volatile(
        "mma.sync.aligned.m16n8k16.row.col.f32.bf16.bf16.f32 "
        "{%0,%1,%2,%3}, {%4,%5,%6,%7}, {%8,%9}, {%0,%1,%2,%3};"
        : "+f"(c[0]), "+f"(c[1]), "+f"(c[2]), "+f"(c[3])
        : "r"(a0), "r"(a1), "r"(a2), "r"(a3), "r"(b0), "r"(b1));
}

__device__ __forceinline__ void split_pack(float4 v, uint2& hi, uint2& lo) {
    float f[4] = {v.x, v.y, v.z, v.w};
    __nv_bfloat16 h[4], l[4];
#pragma unroll
    for (int j = 0; j < 4; ++j) {
        h[j] = __float2bfloat16_rn(f[j]);
        l[j] = __float2bfloat16_rn(f[j] - __bfloat162float(h[j]));
    }
    __nv_bfloat162 h01 = __halves2bfloat162(h[0], h[1]);
    __nv_bfloat162 h23 = __halves2bfloat162(h[2], h[3]);
    __nv_bfloat162 l01 = __halves2bfloat162(l[0], l[1]);
    __nv_bfloat162 l23 = __halves2bfloat162(l[2], l[3]);
    hi.x = *reinterpret_cast<uint32_t*>(&h01);
    hi.y = *reinterpret_cast<uint32_t*>(&h23);
    lo.x = *reinterpret_cast<uint32_t*>(&l01);
    lo.y = *reinterpret_cast<uint32_t*>(&l23);
}

// ---------------------------------------------------------------------------
// Persistent GEMM: grid = #SMs, 256 threads. Warp w owns rows [w*16, w*16+16).
// ---------------------------------------------------------------------------
__global__ __launch_bounds__(256, 1)
void gemm_persist_kernel(const float* __restrict__ x,
                         const float* __restrict__ W,
                         const float* __restrict__ a,
                         float* __restrict__ h_out,
                         int N, int tiles)
{
    extern __shared__ char smem[];
    float*    As   = reinterpret_cast<float*>(smem + SM_AVEC);
    uint32_t* Bh   = reinterpret_cast<uint32_t*>(smem + SM_B_HI);
    uint32_t* Bl   = reinterpret_cast<uint32_t*>(smem + SM_B_LO);
    uint32_t* Ah   = reinterpret_cast<uint32_t*>(smem + SM_A_HI);
    uint32_t* Al   = reinterpret_cast<uint32_t*>(smem + SM_A_LO);
    float4*   Xraw = reinterpret_cast<float4*>(smem + SM_XRAW);
    const uint32_t xraw_u32 = smem_u32(smem + SM_XRAW);

    const int tid  = threadIdx.x;
    const int wid  = tid >> 5;
    const int lane = tid & 31;
    const int qr   = lane >> 2;
    const int qc   = lane & 3;

    // ---- helper: async-copy one x tile (row0) into Xraw ----
    auto issue_copy = [&](int row0) {
#pragma unroll
        for (int it = 0; it < 16; ++it) {
            int idx = it * 256 + tid;          // 4096 float4
            int r   = idx >> 5;
            int c4  = idx & 31;
            int rg  = row0 + r;
            if (rg >= N) rg = N - 1;           // clamp (stores guarded later)
            const float4* src =
                reinterpret_cast<const float4*>(x) + (size_t)rg * 32 + c4;
            uint32_t dst = xraw_u32 + (uint32_t)idx * 16u;
            asm volatile("cp.async.cg.shared.global [%0], [%1], 16;"
                         :: "r"(dst), "l"(src) : "memory");
        }
        asm volatile("cp.async.commit_group;" ::: "memory");
    };

    int t = blockIdx.x;
    if (t < tiles) issue_copy(t * TILE_M);     // prefetch first tile

    // ---- W (64x128 fp32) -> B_hi/B_lo, once per CTA ----
#pragma unroll
    for (int it = 0; it < 8; ++it) {
        int idx = it * 256 + tid;              // 2048 float4
        int n   = idx >> 5;
        int c4  = idx & 31;
        float4 v = reinterpret_cast<const float4*>(W)[n * 32 + c4];
        uint2 hi, lo;
        split_pack(v, hi, lo);
        int w = n * PITCHW + c4 * 2;
        *reinterpret_cast<uint2*>(Bh + w) = hi;
        *reinterpret_cast<uint2*>(Bl + w) = lo;
    }
    if (tid < 2 * F_OUT) As[tid] = a[tid];

    // ---- persistent tile loop ----
    for (; t < tiles; t += gridDim.x) {
        const int row0 = t * TILE_M;

        asm volatile("cp.async.wait_group 0;" ::: "memory");
        __syncthreads();   // x tile arrived; prev iter fully done (A reusable)

        // convert Xraw -> A_hi/A_lo
#pragma unroll
        for (int it = 0; it < 16; ++it) {
            int idx = it * 256 + tid;
            float4 v = Xraw[idx];
            uint2 hi, lo;
            split_pack(v, hi, lo);
            int w = (idx >> 5) * PITCHW + (idx & 31) * 2;
            *reinterpret_cast<uint2*>(Ah + w) = hi;
            *reinterpret_cast<uint2*>(Al + w) = lo;
        }
        __syncthreads();   // A ready; Xraw free

        int tn = t + gridDim.x;
        if (tn < tiles) issue_copy(tn * TILE_M);   // overlaps MMA below

        // ---- MMA: 1 m16 frag x 8 n8 frags x 8 k16 steps x 3 chains ----
        float c[8][4];
#pragma unroll
        for (int j = 0; j < 8; ++j)
#pragma unroll
            for (int q = 0; q < 4; ++q) c[j][q] = 0.f;

        const int arow = wid * 16 + qr;
#pragma unroll
        for (int kk = 0; kk < 8; ++kk) {
            int kw = kk * 8 + qc;
            int base = arow * PITCHW + kw;
            uint32_t ah0 = Ah[base],               ah1 = Ah[base + 8 * PITCHW];
            uint32_t ah2 = Ah[base + 4],           ah3 = Ah[base + 8 * PITCHW + 4];
            uint32_t al0 = Al[base],               al1 = Al[base + 8 * PITCHW];
            uint32_t al2 = Al[base + 4],           al3 = Al[base + 8 * PITCHW + 4];
#pragma unroll
            for (int j = 0; j < 8; ++j) {
                int bbase = (j * 8 + qr) * PITCHW + kw;
                uint32_t bh0 = Bh[bbase], bh1 = Bh[bbase + 4];
                uint32_t bl0 = Bl[bbase], bl1 = Bl[bbase + 4];
                mma_bf16(c[j], ah0, ah1, ah2, ah3, bh0, bh1);   // hi*hi
                mma_bf16(c[j], al0, al1, al2, al3, bh0, bh1);   // lo*hi
                mma_bf16(c[j], ah0, ah1, ah2, ah3, bl0, bl1);   // hi*lo
            }
        }

        // ---- epilogue: write h, fold s1/s2 ----
        {
            float s1a = 0.f, s2a = 0.f, s1b = 0.f, s2b = 0.f;
            int ra = row0 + wid * 16 + qr;
            int rb = ra + 8;
#pragma unroll
            for (int j = 0; j < 8; ++j) {
                int n = j * 8 + qc * 2;
                float a1v = As[n],         a2v = As[n + 1];
                float b1v = As[F_OUT + n], b2v = As[F_OUT + n + 1];
                float* cc = c[j];
                if (ra < N)
                    *reinterpret_cast<float2*>(h_out + (size_t)ra * F_OUT + n) =
                        make_float2(cc[0], cc[1]);
                if (rb < N)
                    *reinterpret_cast<float2*>(h_out + (size_t)rb * F_OUT + n) =
                        make_float2(cc[2], cc[3]);
                s1a = fmaf(cc[0], a1v, fmaf(cc[1], a2v, s1a));
                s2a = fmaf(cc[0], b1v, fmaf(cc[1], b2v, s2a));
                s1b = fmaf(cc[2], a1v, fmaf(cc[3], a2v, s1b));
                s2b = fmaf(cc[2], b1v, fmaf(cc[3], b2v, s2b));
            }
#pragma unroll
            for (int off = 1; off <= 2; off <<= 1) {
                s1a += __shfl_xor_sync(0xFFFFFFFFu, s1a, off);
                s2a += __shfl_xor_sync(0xFFFFFFFFu, s2a, off);
                s1b += __shfl_xor_sync(0xFFFFFFFFu, s1b, off);
                s2b += __shfl_xor_sync(0xFFFFFFFFu, s2b, off);
            }
            if (qc == 0) {
                if (ra < N) g_s12[ra] = make_float2(s1a, s2a);
                if (rb < N) g_s12[rb] = make_float2(s1b, s2b);
            }
        }
    }
}

// ---------------------------------------------------------------------------
// Edge attention: one warp handles 4 edges (4 gathers in flight).
// ---------------------------------------------------------------------------
__global__ __launch_bounds__(256)
void edge_attn_kernel(const int* __restrict__ nodes,
                      float* __restrict__ ea_out,
                      int H)
{
    int gw   = (blockIdx.x * 256 + threadIdx.x) >> 5;   // global warp id
    int lane = threadIdx.x & 31;
    int e0   = gw * 4;
    if (e0 >= H) return;

    float wl = (float)(DEG - 1 - lane);
    float wr = (float)lane;

    float v[4];
    int   nd[4];
#pragma unroll
    for (int i = 0; i < 4; ++i) {
        int e = e0 + i;
        nd[i] = (e < H) ? nodes[e * DEG + lane] : 0;
    }
#pragma unroll
    for (int i = 0; i < 4; ++i) {
        float2 s = g_s12[nd[i]];
        v[i] = s.x * wl + s.y * wr;
    }
#pragma unroll
    for (int off = 16; off > 0; off >>= 1) {
#pragma unroll
        for (int i = 0; i < 4; ++i)
            v[i] += __shfl_xor_sync(0xFFFFFFFFu, v[i], off);
    }
    if (lane == 0) {
        if (e0 + 3 < H) {
            *reinterpret_cast<float4*>(ea_out + e0) =
                make_float4(v[0] * (1.0f / NPAIRS), v[1] * (1.0f / NPAIRS),
                            v[2] * (1.0f / NPAIRS), v[3] * (1.0f / NPAIRS));
        } else {
#pragma unroll
            for (int i = 0; i < 4; ++i)
                if (e0 + i < H) ea_out[e0 + i] = v[i] * (1.0f / NPAIRS);
        }
    }
}

// ---------------------------------------------------------------------------
extern "C" void kernel_launch(void* const* d_in, const int* in_sizes, int n_in,
                              void* d_out, int out_size)
{
    const float* x    = (const float*)d_in[0];
    const float* W    = (const float*)d_in[1];
    const float* a    = (const float*)d_in[2];
    const int*   hidx = (const int*)d_in[3];

    int N = in_sizes[0] / F_IN;    // 200000
    int E = in_sizes[3] / 2;       // 1,600,000
    int H = E / DEG;               // 50000

    float* h_out  = (float*)d_out;
    float* ea_out = (float*)d_out + (size_t)N * F_OUT;
    const int* nodes = hidx;

    int sms = 0;
    cudaDeviceGetAttribute(&sms, cudaDevAttrMultiProcessorCount, 0);
    if (sms <= 0) sms = 148;

    cudaFuncSetAttribute(gemm_persist_kernel,
                         cudaFuncAttributeMaxDynamicSharedMemorySize, SM_TOTAL);

    int tiles = (N + TILE_M - 1) / TILE_M;    // 1563
    gemm_persist_kernel<<<sms, 256, SM_TOTAL>>>(x, W, a, h_out, N, tiles);

    {
        int warps  = (H + 3) / 4;
        int blocks = (warps * 32 + 255) / 256;
        edge_attn_kernel<<<blocks, 256>>>(nodes, ea_out, H);
    }
}

// round 5
// speedup vs baseline: 3.8338x; 1.1792x over previous
#include <cuda_runtime.h>
#include <cuda_fp16.h>
#include <cstdint>

// ---------------------------------------------------------------------------
// HypergraphAttentionLayer on GB300 (sm_103a), portable-PTX tensor path.
// (harness lowers via compute_103 -> no tcgen05; use mma.sync fp16 HMMA)
//   h ~= fp16(x) * (W_hi + W_lo)    (fp16 2-chain, x-quant err ~2^-11)
//   s1/s2 fused in epilogue; ea[e] = (sum_r s1*(31-r)+s2*r)/496
// Persistent GEMM, double-buffered cp.async x staging.
// ---------------------------------------------------------------------------

#define F_IN   128
#define F_OUT  64
#define DEG    32
#define NPAIRS 496.0f
#define MAX_N  200704
#define TILE_M 128
#define PITCHW 68       // 32-bit words per smem row of fp16 (64 + 4 pad)

__device__ float2 g_s12[MAX_N];

// smem byte offsets
#define SM_AVEC 0                        // 512 B
#define SM_B_HI 512                      // 64*68*4  = 17408
#define SM_B_LO (SM_B_HI + 17408)
#define SM_A    (SM_B_LO + 17408)        // 128*68*4 = 34816 (fp16 x tile)
#define SM_X0   (SM_A + 34816)           // 128*128*4 = 65536
#define SM_X1   (SM_X0 + 65536)
#define SM_TOTAL (SM_X1 + 65536)         // 201216 B

__device__ __forceinline__ uint32_t smem_u32(const void* p) {
    uint32_t a;
    asm("{ .reg .u64 t; cvta.to.shared.u64 t, %1; cvt.u32.u64 %0, t; }"
        : "=r"(a) : "l"(p));
    return a;
}

__device__ __forceinline__ void mma_f16(float c[4],
                                        uint32_t a0, uint32_t a1,
                                        uint32_t a2, uint32_t a3,
                                        uint32_t b0, uint32_t b1)
{
    asm volatile(
        "mma.sync.aligned.m16n8k16.row.col.f32.f16.f16.f32 "
        "{%0,%1,%2,%3}, {%4,%5,%6,%7}, {%8,%9}, {%0,%1,%2,%3};"
        : "+f"(c[0]), "+f"(c[1]), "+f"(c[2]), "+f"(c[3])
        : "r"(a0), "r"(a1), "r"(a2), "r"(a3), "r"(b0), "r"(b1));
}

// W split: hi = fp16(w), lo = fp16(w - hi)
__device__ __forceinline__ void split_pack_h(float4 v, uint2& hi, uint2& lo) {
    __half h[4], l[4];
    float f[4] = {v.x, v.y, v.z, v.w};
#pragma unroll
    for (int j = 0; j < 4; ++j) {
        h[j] = __float2half_rn(f[j]);
        l[j] = __float2half_rn(f[j] - __half2float(h[j]));
    }
    __half2 h01 = __halves2half2(h[0], h[1]);
    __half2 h23 = __halves2half2(h[2], h[3]);
    __half2 l01 = __halves2half2(l[0], l[1]);
    __half2 l23 = __halves2half2(l[2], l[3]);
    hi.x = *reinterpret_cast<uint32_t*>(&h01);
    hi.y = *reinterpret_cast<uint32_t*>(&h23);
    lo.x = *reinterpret_cast<uint32_t*>(&l01);
    lo.y = *reinterpret_cast<uint32_t*>(&l23);
}

// ---------------------------------------------------------------------------
// Persistent GEMM: grid = #SMs, 256 threads. Warp w owns rows [w*16, w*16+16).
// ---------------------------------------------------------------------------
__global__ __launch_bounds__(256, 1)
void gemm_persist_kernel(const float* __restrict__ x,
                         const float* __restrict__ W,
                         const float* __restrict__ a,
                         float* __restrict__ h_out,
                         int N, int tiles)
{
    extern __shared__ char smem[];
    float*    As = reinterpret_cast<float*>(smem + SM_AVEC);
    uint32_t* Bh = reinterpret_cast<uint32_t*>(smem + SM_B_HI);
    uint32_t* Bl = reinterpret_cast<uint32_t*>(smem + SM_B_LO);
    uint32_t* A  = reinterpret_cast<uint32_t*>(smem + SM_A);
    const uint32_t x0_u32 = smem_u32(smem + SM_X0);

    const int tid  = threadIdx.x;
    const int wid  = tid >> 5;
    const int lane = tid & 31;
    const int qr   = lane >> 2;
    const int qc   = lane & 3;
    const int g    = gridDim.x;

    // async-copy one x tile into buffer b (0/1)
    auto issue_copy = [&](int row0, int b) {
        uint32_t base = x0_u32 + (uint32_t)b * 65536u;
#pragma unroll
        for (int it = 0; it < 16; ++it) {
            int idx = it * 256 + tid;          // 4096 float4
            int r   = idx >> 5;
            int c4  = idx & 31;
            int rg  = row0 + r;
            if (rg >= N) rg = N - 1;           // clamp (stores guarded later)
            const float4* src =
                reinterpret_cast<const float4*>(x) + (size_t)rg * 32 + c4;
            asm volatile("cp.async.cg.shared.global [%0], [%1], 16;"
                         :: "r"(base + (uint32_t)idx * 16u), "l"(src) : "memory");
        }
        asm volatile("cp.async.commit_group;" ::: "memory");
    };

    // prefetch two tiles
    if (blockIdx.x < tiles)     issue_copy(blockIdx.x * TILE_M, 0);
    if (blockIdx.x + g < tiles) issue_copy((blockIdx.x + g) * TILE_M, 1);

    // ---- W (64x128 fp32) -> B_hi/B_lo fp16, once per CTA ----
#pragma unroll
    for (int it = 0; it < 8; ++it) {
        int idx = it * 256 + tid;              // 2048 float4
        int n   = idx >> 5;
        int c4  = idx & 31;
        float4 v = reinterpret_cast<const float4*>(W)[n * 32 + c4];
        uint2 hi, lo;
        split_pack_h(v, hi, lo);
        int w = n * PITCHW + c4 * 2;
        *reinterpret_cast<uint2*>(Bh + w) = hi;
        *reinterpret_cast<uint2*>(Bl + w) = lo;
    }
    if (tid < 2 * F_OUT) As[tid] = a[tid];

    // ---- persistent tile loop ----
    int buf = 0;
    for (int t = blockIdx.x; t < tiles; t += g, buf ^= 1) {
        const int row0 = t * TILE_M;

        if (t + g < tiles)
            asm volatile("cp.async.wait_group 1;" ::: "memory");
        else
            asm volatile("cp.async.wait_group 0;" ::: "memory");
        __syncthreads();   // x tile arrived; all warps done with A from prev iter

        // convert Xraw[buf] (fp32) -> A (fp16)
        const float4* Xb =
            reinterpret_cast<const float4*>(smem + SM_X0 + buf * 65536);
#pragma unroll
        for (int it = 0; it < 16; ++it) {
            int idx = it * 256 + tid;
            float4 v = Xb[idx];
            __half2 p01 = __floats2half2_rn(v.x, v.y);
            __half2 p23 = __floats2half2_rn(v.z, v.w);
            uint2 pk;
            pk.x = *reinterpret_cast<uint32_t*>(&p01);
            pk.y = *reinterpret_cast<uint32_t*>(&p23);
            int w = (idx >> 5) * PITCHW + (idx & 31) * 2;
            *reinterpret_cast<uint2*>(A + w) = pk;
        }
        __syncthreads();   // A ready; Xraw[buf] free

        if (t + 2 * g < tiles) issue_copy((t + 2 * g) * TILE_M, buf);

        // ---- MMA: 1 m16 frag x 8 n8 frags x 8 k16 steps x 2 chains ----
        float c[8][4];
#pragma unroll
        for (int j = 0; j < 8; ++j)
#pragma unroll
            for (int q = 0; q < 4; ++q) c[j][q] = 0.f;

        const int arow = wid * 16 + qr;
#pragma unroll
        for (int kk = 0; kk < 8; ++kk) {
            int kw = kk * 8 + qc;
            int base = arow * PITCHW + kw;
            uint32_t a0 = A[base];
            uint32_t a1 = A[base + 8 * PITCHW];
            uint32_t a2 = A[base + 4];
            uint32_t a3 = A[base + 8 * PITCHW + 4];
#pragma unroll
            for (int j = 0; j < 8; ++j) {
                int bbase = (j * 8 + qr) * PITCHW + kw;
                uint32_t bh0 = Bh[bbase], bh1 = Bh[bbase + 4];
                uint32_t bl0 = Bl[bbase], bl1 = Bl[bbase + 4];
                mma_f16(c[j], a0, a1, a2, a3, bh0, bh1);   // x*W_hi
                mma_f16(c[j], a0, a1, a2, a3, bl0, bl1);   // x*W_lo
            }
        }

        // ---- epilogue: write h, fold s1/s2 ----
        {
            float s1a = 0.f, s2a = 0.f, s1b = 0.f, s2b = 0.f;
            int ra = row0 + wid * 16 + qr;
            int rb = ra + 8;
#pragma unroll
            for (int j = 0; j < 8; ++j) {
                int n = j * 8 + qc * 2;
                float a1v = As[n],         a2v = As[n + 1];
                float b1v = As[F_OUT + n], b2v = As[F_OUT + n + 1];
                float* cc = c[j];
                if (ra < N)
                    *reinterpret_cast<float2*>(h_out + (size_t)ra * F_OUT + n) =
                        make_float2(cc[0], cc[1]);
                if (rb < N)
                    *reinterpret_cast<float2*>(h_out + (size_t)rb * F_OUT + n) =
                        make_float2(cc[2], cc[3]);
                s1a = fmaf(cc[0], a1v, fmaf(cc[1], a2v, s1a));
                s2a = fmaf(cc[0], b1v, fmaf(cc[1], b2v, s2a));
                s1b = fmaf(cc[2], a1v, fmaf(cc[3], a2v, s1b));
                s2b = fmaf(cc[2], b1v, fmaf(cc[3], b2v, s2b));
            }
#pragma unroll
            for (int off = 1; off <= 2; off <<= 1) {
                s1a += __shfl_xor_sync(0xFFFFFFFFu, s1a, off);
                s2a += __shfl_xor_sync(0xFFFFFFFFu, s2a, off);
                s1b += __shfl_xor_sync(0xFFFFFFFFu, s1b, off);
                s2b += __shfl_xor_sync(0xFFFFFFFFu, s2b, off);
            }
            if (qc == 0) {
                if (ra < N) g_s12[ra] = make_float2(s1a, s2a);
                if (rb < N) g_s12[rb] = make_float2(s1b, s2b);
            }
        }
    }
}

// ---------------------------------------------------------------------------
// Edge attention: one warp = 4 edges. One LDG.128 fetches all 128 node ids;
// lane l holds ranks (4l..4l+3) mod 32 of edge l/8; reduce over octs.
// ---------------------------------------------------------------------------
__global__ __launch_bounds__(256)
void edge_attn_kernel(const int* __restrict__ nodes,
                      float* __restrict__ ea_out,
                      int H)
{
    int gw   = (blockIdx.x * 256 + threadIdx.x) >> 5;
    int lane = threadIdx.x & 31;
    int e0   = gw * 4;
    if (e0 >= H) return;

    int e    = e0 + (lane >> 3);          // this lane's edge
    bool ok  = (e < H);

    int4 nd = ok
        ? reinterpret_cast<const int4*>(nodes + (size_t)e0 * DEG)[lane]
        : make_int4(0, 0, 0, 0);

    int r0 = (lane * 4) & 31;             // rank of nd.x within its edge
    float2 s0 = g_s12[nd.x];
    float2 s1 = g_s12[nd.y];
    float2 s2 = g_s12[nd.z];
    float2 s3 = g_s12[nd.w];

    float v = s0.x * (float)(31 - r0)     + s0.y * (float)(r0)
            + s1.x * (float)(31 - r0 - 1) + s1.y * (float)(r0 + 1)
            + s2.x * (float)(31 - r0 - 2) + s2.y * (float)(r0 + 2)
            + s3.x * (float)(31 - r0 - 3) + s3.y * (float)(r0 + 3);

#pragma unroll
    for (int off = 1; off <= 4; off <<= 1)
        v += __shfl_xor_sync(0xFFFFFFFFu, v, off);

    if ((lane & 7) == 0 && ok)
        ea_out[e] = v * (1.0f / NPAIRS);
}

// ---------------------------------------------------------------------------
extern "C" void kernel_launch(void* const* d_in, const int* in_sizes, int n_in,
                              void* d_out, int out_size)
{
    const float* x    = (const float*)d_in[0];
    const float* W    = (const float*)d_in[1];
    const float* a    = (const float*)d_in[2];
    const int*   hidx = (const int*)d_in[3];

    int N = in_sizes[0] / F_IN;    // 200000
    int E = in_sizes[3] / 2;       // 1,600,000
    int H = E / DEG;               // 50000

    float* h_out  = (float*)d_out;
    float* ea_out = (float*)d_out + (size_t)N * F_OUT;
    const int* nodes = hidx;

    int sms = 0;
    cudaDeviceGetAttribute(&sms, cudaDevAttrMultiProcessorCount, 0);
    if (sms <= 0) sms = 148;

    cudaFuncSetAttribute(gemm_persist_kernel,
                         cudaFuncAttributeMaxDynamicSharedMemorySize, SM_TOTAL);

    int tiles = (N + TILE_M - 1) / TILE_M;    // 1563
    gemm_persist_kernel<<<sms, 256, SM_TOTAL>>>(x, W, a, h_out, N, tiles);

    {
        int warps  = (H + 3) / 4;             // 12500
        int blocks = (warps * 32 + 255) / 256;
        edge_attn_kernel<<<blocks, 256>>>(nodes, ea_out, H);
    }
}

// round 6
// speedup vs baseline: 4.7922x; 1.2500x over previous
#include <cuda_runtime.h>
#include <cuda_fp16.h>
#include <cstdint>

// ---------------------------------------------------------------------------
// HypergraphAttentionLayer on GB300 (sm_103a), portable-PTX tensor path.
//   h ~= fp16(x) * fp16(W)   (1-chain fp16 HMMA; est. rel_err ~3e-4 vs 1e-3)
//   s1/s2 fused in epilogue; ea[e] = (sum_r s1*(31-r)+s2*r)/496
// Persistent GEMM with WARP-AUTONOMOUS pipelining: each warp owns 16 rows,
// its own cp.async double buffer, its own A slice -> no CTA barriers in loop.
// ---------------------------------------------------------------------------

#define F_IN   128
#define F_OUT  64
#define DEG    32
#define NPAIRS 496.0f
#define MAX_N  200704
#define TILE_M 128
#define PITCHW 68       // 32-bit words per fp16 smem row (64 + 4 pad)

__device__ float2 g_s12[MAX_N];

// smem byte offsets
#define SM_AVEC 0                        // 512 B
#define SM_B    512                      // 64*68*4  = 17408 (fp16 W)
#define SM_A    (SM_B + 17408)           // 8*16*68*4 = 34816 (fp16 x, per-warp)
#define SM_X0   (SM_A + 34816)           // 8 warps * 2 bufs * 8192 = 131072
#define SM_TOTAL (SM_X0 + 131072)        // 183808 B

__device__ __forceinline__ uint32_t smem_u32(const void* p) {
    uint32_t a;
    asm("{ .reg .u64 t; cvta.to.shared.u64 t, %1; cvt.u32.u64 %0, t; }"
        : "=r"(a) : "l"(p));
    return a;
}

__device__ __forceinline__ void mma_f16(float c[4],
                                        uint32_t a0, uint32_t a1,
                                        uint32_t a2, uint32_t a3,
                                        uint32_t b0, uint32_t b1)
{
    asm volatile(
        "mma.sync.aligned.m16n8k16.row.col.f32.f16.f16.f32 "
        "{%0,%1,%2,%3}, {%4,%5,%6,%7}, {%8,%9}, {%0,%1,%2,%3};"
        : "+f"(c[0]), "+f"(c[1]), "+f"(c[2]), "+f"(c[3])
        : "r"(a0), "r"(a1), "r"(a2), "r"(a3), "r"(b0), "r"(b1));
}

__device__ __forceinline__ uint2 pack_h4(float4 v) {
    __half2 p01 = __floats2half2_rn(v.x, v.y);
    __half2 p23 = __floats2half2_rn(v.z, v.w);
    uint2 pk;
    pk.x = *reinterpret_cast<uint32_t*>(&p01);
    pk.y = *reinterpret_cast<uint32_t*>(&p23);
    return pk;
}

// ---------------------------------------------------------------------------
// Persistent GEMM: grid = #SMs, 256 threads (8 warps). Warp w owns rows
// [t*128 + w*16, +16) of tile t; fully self-pipelined via its own cp.async.
// ---------------------------------------------------------------------------
__global__ __launch_bounds__(256, 1)
void gemm_persist_kernel(const float* __restrict__ x,
                         const float* __restrict__ W,
                         const float* __restrict__ a,
                         float* __restrict__ h_out,
                         int N, int tiles)
{
    extern __shared__ char smem[];
    float*    As = reinterpret_cast<float*>(smem + SM_AVEC);
    uint32_t* B  = reinterpret_cast<uint32_t*>(smem + SM_B);
    uint32_t* A  = reinterpret_cast<uint32_t*>(smem + SM_A);

    const int tid  = threadIdx.x;
    const int wid  = tid >> 5;
    const int lane = tid & 31;
    const int qr   = lane >> 2;
    const int qc   = lane & 3;
    const int g    = gridDim.x;

    // per-warp Xraw slice: 2 buffers of 16 rows x 128 floats (8192 B each)
    const uint32_t xw_u32 = smem_u32(smem + SM_X0) + (uint32_t)wid * 16384u;

    // async-copy this warp's 16 rows of tile at row0 into buffer b
    auto issue_copy = [&](int row0, int b) {
        uint32_t base = xw_u32 + (uint32_t)b * 8192u;
        int r0 = row0 + wid * 16;
#pragma unroll
        for (int it = 0; it < 16; ++it) {
            int idx = it * 32 + lane;          // 512 float4 per warp
            int rg  = r0 + (idx >> 5);
            if (rg >= N) rg = N - 1;           // clamp (stores guarded later)
            const float4* src =
                reinterpret_cast<const float4*>(x) + (size_t)rg * 32 + (idx & 31);
            asm volatile("cp.async.cg.shared.global [%0], [%1], 16;"
                         :: "r"(base + (uint32_t)idx * 16u), "l"(src) : "memory");
        }
        asm volatile("cp.async.commit_group;" ::: "memory");
    };

    // prefetch two tiles (per warp, own rows)
    if (blockIdx.x < tiles)     issue_copy(blockIdx.x * TILE_M, 0);
    if (blockIdx.x + g < tiles) issue_copy((blockIdx.x + g) * TILE_M, 1);

    // ---- W (64x128 fp32) -> fp16, once per CTA (cooperative) ----
#pragma unroll
    for (int it = 0; it < 8; ++it) {
        int idx = it * 256 + tid;              // 2048 float4
        int n   = idx >> 5;
        int c4  = idx & 31;
        float4 v = reinterpret_cast<const float4*>(W)[n * 32 + c4];
        *reinterpret_cast<uint2*>(B + n * PITCHW + c4 * 2) = pack_h4(v);
    }
    if (tid < 2 * F_OUT) As[tid] = a[tid];
    __syncthreads();                            // B ready for all warps

    // ---- warp-autonomous persistent loop (no CTA barriers) ----
    int buf = 0;
    for (int t = blockIdx.x; t < tiles; t += g, buf ^= 1) {
        const int row0 = t * TILE_M;

        if (t + g < tiles)
            asm volatile("cp.async.wait_group 1;" ::: "memory");
        else
            asm volatile("cp.async.wait_group 0;" ::: "memory");

        // convert my Xraw[buf] -> my A slice (lane reads only its own chunks)
        const float4* Xb = reinterpret_cast<const float4*>(
            smem + SM_X0 + wid * 16384 + buf * 8192);
        uint32_t* Aw = A + wid * 16 * PITCHW;
#pragma unroll
        for (int it = 0; it < 16; ++it) {
            int idx = it * 32 + lane;
            *reinterpret_cast<uint2*>(Aw + (idx >> 5) * PITCHW + (idx & 31) * 2) =
                pack_h4(Xb[idx]);
        }
        __syncwarp();                           // A slice visible warp-wide

        if (t + 2 * g < tiles) issue_copy((t + 2 * g) * TILE_M, buf);

        // ---- MMA: 1 m16 frag x 8 n8 frags x 8 k16 steps, 1 chain ----
        float c[8][4];
#pragma unroll
        for (int j = 0; j < 8; ++j)
#pragma unroll
            for (int q = 0; q < 4; ++q) c[j][q] = 0.f;

        const int arow = wid * 16 + qr;
#pragma unroll
        for (int kk = 0; kk < 8; ++kk) {
            int kw = kk * 8 + qc;
            int base = arow * PITCHW + kw;
            uint32_t a0 = A[base];
            uint32_t a1 = A[base + 8 * PITCHW];
            uint32_t a2 = A[base + 4];
            uint32_t a3 = A[base + 8 * PITCHW + 4];
#pragma unroll
            for (int j = 0; j < 8; ++j) {
                int bb = (j * 8 + qr) * PITCHW + kw;
                mma_f16(c[j], a0, a1, a2, a3, B[bb], B[bb + 4]);
            }
        }

        // ---- epilogue: write h, fold s1/s2 ----
        {
            float s1a = 0.f, s2a = 0.f, s1b = 0.f, s2b = 0.f;
            int ra = row0 + wid * 16 + qr;
            int rb = ra + 8;
#pragma unroll
            for (int j = 0; j < 8; ++j) {
                int n = j * 8 + qc * 2;
                float a1v = As[n],         a2v = As[n + 1];
                float b1v = As[F_OUT + n], b2v = As[F_OUT + n + 1];
                float* cc = c[j];
                if (ra < N)
                    *reinterpret_cast<float2*>(h_out + (size_t)ra * F_OUT + n) =
                        make_float2(cc[0], cc[1]);
                if (rb < N)
                    *reinterpret_cast<float2*>(h_out + (size_t)rb * F_OUT + n) =
                        make_float2(cc[2], cc[3]);
                s1a = fmaf(cc[0], a1v, fmaf(cc[1], a2v, s1a));
                s2a = fmaf(cc[0], b1v, fmaf(cc[1], b2v, s2a));
                s1b = fmaf(cc[2], a1v, fmaf(cc[3], a2v, s1b));
                s2b = fmaf(cc[2], b1v, fmaf(cc[3], b2v, s2b));
            }
#pragma unroll
            for (int off = 1; off <= 2; off <<= 1) {
                s1a += __shfl_xor_sync(0xFFFFFFFFu, s1a, off);
                s2a += __shfl_xor_sync(0xFFFFFFFFu, s2a, off);
                s1b += __shfl_xor_sync(0xFFFFFFFFu, s1b, off);
                s2b += __shfl_xor_sync(0xFFFFFFFFu, s2b, off);
            }
            if (qc == 0) {
                if (ra < N) g_s12[ra] = make_float2(s1a, s2a);
                if (rb < N) g_s12[rb] = make_float2(s1b, s2b);
            }
        }
    }
}

// ---------------------------------------------------------------------------
// Edge attention: one warp = 8 edges. Two LDG.128 fetch 256 node ids;
// each lane gathers 8 float2 (MLP 8); reduce over 8-lane groups (3 shuffles).
// ---------------------------------------------------------------------------
__global__ __launch_bounds__(256)
void edge_attn_kernel(const int* __restrict__ nodes,
                      float* __restrict__ ea_out,
                      int H)
{
    int gw   = (blockIdx.x * 256 + threadIdx.x) >> 5;
    int lane = threadIdx.x & 31;
    int e0   = gw * 8;
    if (e0 >= H) return;

    if (e0 + 8 <= H) {
        const int4* base = reinterpret_cast<const int4*>(nodes + (size_t)e0 * DEG);
        int4 n0 = base[lane];        // edge e0 +     (lane>>3), ranks r0..r0+3
        int4 n1 = base[32 + lane];   // edge e0 + 4 + (lane>>3), ranks r0..r0+3
        int r0 = (lane & 7) * 4;

        float2 s00 = g_s12[n0.x], s01 = g_s12[n0.y];
        float2 s02 = g_s12[n0.z], s03 = g_s12[n0.w];
        float2 s10 = g_s12[n1.x], s11 = g_s12[n1.y];
        float2 s12v = g_s12[n1.z], s13 = g_s12[n1.w];

        float fl = (float)(31 - r0), fr = (float)r0;
        float v0 = s00.x * fl        + s00.y * fr
                 + s01.x * (fl - 1.f) + s01.y * (fr + 1.f)
                 + s02.x * (fl - 2.f) + s02.y * (fr + 2.f)
                 + s03.x * (fl - 3.f) + s03.y * (fr + 3.f);
        float v1 = s10.x * fl        + s10.y * fr
                 + s11.x * (fl - 1.f) + s11.y * (fr + 1.f)
                 + s12v.x * (fl - 2.f) + s12v.y * (fr + 2.f)
                 + s13.x * (fl - 3.f) + s13.y * (fr + 3.f);

#pragma unroll
        for (int off = 1; off <= 4; off <<= 1) {
            v0 += __shfl_xor_sync(0xFFFFFFFFu, v0, off);
            v1 += __shfl_xor_sync(0xFFFFFFFFu, v1, off);
        }
        if ((lane & 7) == 0) {
            int eg = e0 + (lane >> 3);
            ea_out[eg]     = v0 * (1.0f / NPAIRS);
            ea_out[eg + 4] = v1 * (1.0f / NPAIRS);
        }
    } else {
        // tail fallback (unused for H % 8 == 0)
        for (int i = 0; i < 8; ++i) {
            int e = e0 + i;
            if (e >= H) break;
            int node = nodes[(size_t)e * DEG + lane];
            float2 s = g_s12[node];
            float v = s.x * (float)(DEG - 1 - lane) + s.y * (float)lane;
#pragma unroll
            for (int off = 16; off > 0; off >>= 1)
                v += __shfl_xor_sync(0xFFFFFFFFu, v, off);
            if (lane == 0) ea_out[e] = v * (1.0f / NPAIRS);
        }
    }
}

// ---------------------------------------------------------------------------
extern "C" void kernel_launch(void* const* d_in, const int* in_sizes, int n_in,
                              void* d_out, int out_size)
{
    const float* x    = (const float*)d_in[0];
    const float* W    = (const float*)d_in[1];
    const float* a    = (const float*)d_in[2];
    const int*   hidx = (const int*)d_in[3];

    int N = in_sizes[0] / F_IN;    // 200000
    int E = in_sizes[3] / 2;       // 1,600,000
    int H = E / DEG;               // 50000

    float* h_out  = (float*)d_out;
    float* ea_out = (float*)d_out + (size_t)N * F_OUT;
    const int* nodes = hidx;

    int sms = 0;
    cudaDeviceGetAttribute(&sms, cudaDevAttrMultiProcessorCount, 0);
    if (sms <= 0) sms = 148;

    cudaFuncSetAttribute(gemm_persist_kernel,
                         cudaFuncAttributeMaxDynamicSharedMemorySize, SM_TOTAL);

    int tiles = (N + TILE_M - 1) / TILE_M;    // 1563
    gemm_persist_kernel<<<sms, 256, SM_TOTAL>>>(x, W, a, h_out, N, tiles);

    {
        int warps  = (H + 7) / 8;             // 6250
        int blocks = (warps * 32 + 255) / 256;
        edge_attn_kernel<<<blocks, 256>>>(nodes, ea_out, H);
    }
}

// round 7
// speedup vs baseline: 5.0897x; 1.0621x over previous
#include <cuda_runtime.h>
#include <cuda_fp16.h>
#include <cstdint>

// ---------------------------------------------------------------------------
// HypergraphAttentionLayer on GB300 (sm_103a), portable-PTX tensor path.
//   h ~= fp16(x) * fp16(W)   (1-chain fp16 HMMA)
//   s1/s2 fused in epilogue; ea[e] = (sum_r s1*(31-r)+s2*r)/496
// Persistent warp-autonomous GEMM. W fragments held in REGISTERS for the
// whole kernel (loaded once via ldmatrix); A fragments via ldmatrix.x4.
// ---------------------------------------------------------------------------

#define F_IN   128
#define F_OUT  64
#define DEG    32
#define NPAIRS 496.0f
#define MAX_N  200704
#define TILE_M 128
#define PITCHW 68       // 32-bit words per fp16 smem row (64 + 4 pad)
#define PITCHB 272      // bytes per fp16 smem row

__device__ float2 g_s12[MAX_N];

// smem byte offsets
#define SM_AVEC 0                        // 512 B
#define SM_B    512                      // 64*272  = 17408 (fp16 W)
#define SM_A    (SM_B + 17408)           // 128*272 = 34816 (fp16 x)
#define SM_X0   (SM_A + 34816)           // 8 warps * 2 bufs * 8192 = 131072
#define SM_TOTAL (SM_X0 + 131072)        // 183808 B

__device__ __forceinline__ uint32_t smem_u32(const void* p) {
    uint32_t a;
    asm("{ .reg .u64 t; cvta.to.shared.u64 t, %1; cvt.u32.u64 %0, t; }"
        : "=r"(a) : "l"(p));
    return a;
}

__device__ __forceinline__ void mma_f16(float c[4],
                                        uint32_t a0, uint32_t a1,
                                        uint32_t a2, uint32_t a3,
                                        uint32_t b0, uint32_t b1)
{
    asm volatile(
        "mma.sync.aligned.m16n8k16.row.col.f32.f16.f16.f32 "
        "{%0,%1,%2,%3}, {%4,%5,%6,%7}, {%8,%9}, {%0,%1,%2,%3};"
        : "+f"(c[0]), "+f"(c[1]), "+f"(c[2]), "+f"(c[3])
        : "r"(a0), "r"(a1), "r"(a2), "r"(a3), "r"(b0), "r"(b1));
}

__device__ __forceinline__ void ldmatrix_x4(uint32_t& r0, uint32_t& r1,
                                            uint32_t& r2, uint32_t& r3,
                                            uint32_t addr)
{
    asm volatile(
        "ldmatrix.sync.aligned.m8n8.x4.shared.b16 {%0,%1,%2,%3}, [%4];"
        : "=r"(r0), "=r"(r1), "=r"(r2), "=r"(r3) : "r"(addr));
}

__device__ __forceinline__ uint2 pack_h4(float4 v) {
    __half2 p01 = __floats2half2_rn(v.x, v.y);
    __half2 p23 = __floats2half2_rn(v.z, v.w);
    uint2 pk;
    pk.x = *reinterpret_cast<uint32_t*>(&p01);
    pk.y = *reinterpret_cast<uint32_t*>(&p23);
    return pk;
}

// ---------------------------------------------------------------------------
// Persistent GEMM: grid = #SMs, 256 threads (8 warps). Warp w owns rows
// [t*128 + w*16, +16); self-pipelined cp.async; B frags in registers.
// ---------------------------------------------------------------------------
__global__ __launch_bounds__(256, 1)
void gemm_persist_kernel(const float* __restrict__ x,
                         const float* __restrict__ W,
                         const float* __restrict__ a,
                         float* __restrict__ h_out,
                         int N, int tiles)
{
    extern __shared__ char smem[];
    float*    As = reinterpret_cast<float*>(smem + SM_AVEC);
    uint32_t* B  = reinterpret_cast<uint32_t*>(smem + SM_B);
    uint32_t* A  = reinterpret_cast<uint32_t*>(smem + SM_A);

    const int tid  = threadIdx.x;
    const int wid  = tid >> 5;
    const int lane = tid & 31;
    const int qr   = lane >> 2;
    const int qc   = lane & 3;
    const int g    = gridDim.x;

    const uint32_t xw_u32 = smem_u32(smem + SM_X0) + (uint32_t)wid * 16384u;

    auto issue_copy = [&](int row0, int b) {
        uint32_t base = xw_u32 + (uint32_t)b * 8192u;
        int r0 = row0 + wid * 16;
#pragma unroll
        for (int it = 0; it < 16; ++it) {
            int idx = it * 32 + lane;
            int rg  = r0 + (idx >> 5);
            if (rg >= N) rg = N - 1;
            const float4* src =
                reinterpret_cast<const float4*>(x) + (size_t)rg * 32 + (idx & 31);
            asm volatile("cp.async.cg.shared.global [%0], [%1], 16;"
                         :: "r"(base + (uint32_t)idx * 16u), "l"(src) : "memory");
        }
        asm volatile("cp.async.commit_group;" ::: "memory");
    };

    if (blockIdx.x < tiles)     issue_copy(blockIdx.x * TILE_M, 0);
    if (blockIdx.x + g < tiles) issue_copy((blockIdx.x + g) * TILE_M, 1);

    // ---- W (64x128 fp32) -> fp16 smem, once per CTA ----
#pragma unroll
    for (int it = 0; it < 8; ++it) {
        int idx = it * 256 + tid;
        int n   = idx >> 5;
        int c4  = idx & 31;
        float4 v = reinterpret_cast<const float4*>(W)[n * 32 + c4];
        *reinterpret_cast<uint2*>(B + n * PITCHW + c4 * 2) = pack_h4(v);
    }
    if (tid < 2 * F_OUT) As[tid] = a[tid];
    __syncthreads();

    // ---- load ALL B fragments into registers (held for whole kernel) ----
    // bf[kk][j][0/1]: j = n8-frag (n = 8j..8j+7), kk = k16 step
    uint32_t bf[8][8][2];
    {
        // lane addressing for B ldmatrix.x4:
        //  g0 (l 0-7):  rows jp*16 + (l&7),      k-lo   -> b0 of j=2jp
        //  g1 (l 8-15): same rows,               k-hi   -> b1 of j=2jp
        //  g2 (l16-23): rows jp*16+8+(l&7),      k-lo   -> b0 of j=2jp+1
        //  g3 (l24-31): same rows,               k-hi   -> b1 of j=2jp+1
        int rowselB  = (lane & 7) + ((lane >> 4) & 1) * 8;
        int byteselB = ((lane >> 3) & 1) * 16;
        uint32_t b_base = smem_u32(smem + SM_B) + rowselB * PITCHB + byteselB;
#pragma unroll
        for (int jp = 0; jp < 4; ++jp) {
#pragma unroll
            for (int kk = 0; kk < 8; ++kk) {
                ldmatrix_x4(bf[kk][2 * jp][0], bf[kk][2 * jp][1],
                            bf[kk][2 * jp + 1][0], bf[kk][2 * jp + 1][1],
                            b_base + jp * 16 * PITCHB + kk * 32);
            }
        }
    }

    // A ldmatrix lane addressing:
    //  g0: rows +(l&7) k-lo (a0); g1: rows+8 k-lo (a1);
    //  g2: rows +(l&7) k-hi (a2); g3: rows+8 k-hi (a3)
    const int rowselA  = (lane & 7) + ((lane >> 3) & 1) * 8;
    const int byteselA = ((lane >> 4) & 1) * 16;
    const uint32_t a_base = smem_u32(smem + SM_A) +
        (wid * 16 + rowselA) * PITCHB + byteselA;

    // ---- warp-autonomous persistent loop ----
    int buf = 0;
    for (int t = blockIdx.x; t < tiles; t += g, buf ^= 1) {
        const int row0 = t * TILE_M;

        if (t + g < tiles)
            asm volatile("cp.async.wait_group 1;" ::: "memory");
        else
            asm volatile("cp.async.wait_group 0;" ::: "memory");

        // convert my Xraw[buf] -> my A slice
        const float4* Xb = reinterpret_cast<const float4*>(
            smem + SM_X0 + wid * 16384 + buf * 8192);
        uint32_t* Aw = A + wid * 16 * PITCHW;
#pragma unroll
        for (int it = 0; it < 16; ++it) {
            int idx = it * 32 + lane;
            *reinterpret_cast<uint2*>(Aw + (idx >> 5) * PITCHW + (idx & 31) * 2) =
                pack_h4(Xb[idx]);
        }
        __syncwarp();

        if (t + 2 * g < tiles) issue_copy((t + 2 * g) * TILE_M, buf);

        // ---- MMA: ldmatrix A frags, B frags from registers ----
        float c[8][4];
#pragma unroll
        for (int j = 0; j < 8; ++j)
#pragma unroll
            for (int q = 0; q < 4; ++q) c[j][q] = 0.f;

#pragma unroll
        for (int kk = 0; kk < 8; ++kk) {
            uint32_t a0, a1, a2, a3;
            ldmatrix_x4(a0, a1, a2, a3, a_base + kk * 32);
#pragma unroll
            for (int j = 0; j < 8; ++j)
                mma_f16(c[j], a0, a1, a2, a3, bf[kk][j][0], bf[kk][j][1]);
        }

        // ---- epilogue: write h, fold s1/s2 ----
        {
            float s1a = 0.f, s2a = 0.f, s1b = 0.f, s2b = 0.f;
            int ra = row0 + wid * 16 + qr;
            int rb = ra + 8;
#pragma unroll
            for (int j = 0; j < 8; ++j) {
                int n = j * 8 + qc * 2;
                float a1v = As[n],         a2v = As[n + 1];
                float b1v = As[F_OUT + n], b2v = As[F_OUT + n + 1];
                float* cc = c[j];
                if (ra < N)
                    *reinterpret_cast<float2*>(h_out + (size_t)ra * F_OUT + n) =
                        make_float2(cc[0], cc[1]);
                if (rb < N)
                    *reinterpret_cast<float2*>(h_out + (size_t)rb * F_OUT + n) =
                        make_float2(cc[2], cc[3]);
                s1a = fmaf(cc[0], a1v, fmaf(cc[1], a2v, s1a));
                s2a = fmaf(cc[0], b1v, fmaf(cc[1], b2v, s2a));
                s1b = fmaf(cc[2], a1v, fmaf(cc[3], a2v, s1b));
                s2b = fmaf(cc[2], b1v, fmaf(cc[3], b2v, s2b));
            }
#pragma unroll
            for (int off = 1; off <= 2; off <<= 1) {
                s1a += __shfl_xor_sync(0xFFFFFFFFu, s1a, off);
                s2a += __shfl_xor_sync(0xFFFFFFFFu, s2a, off);
                s1b += __shfl_xor_sync(0xFFFFFFFFu, s1b, off);
                s2b += __shfl_xor_sync(0xFFFFFFFFu, s2b, off);
            }
            if (qc == 0) {
                if (ra < N) g_s12[ra] = make_float2(s1a, s2a);
                if (rb < N) g_s12[rb] = make_float2(s1b, s2b);
            }
        }
    }
}

// ---------------------------------------------------------------------------
// Edge attention: one warp = 16 edges. 4 LDG.128 fetch 512 node ids;
// each lane gathers 16 float2 (MLP 16); reduce over 8-lane groups.
// ---------------------------------------------------------------------------
__global__ __launch_bounds__(256)
void edge_attn_kernel(const int* __restrict__ nodes,
                      float* __restrict__ ea_out,
                      int H)
{
    int gw   = (blockIdx.x * 256 + threadIdx.x) >> 5;
    int lane = threadIdx.x & 31;
    int e0   = gw * 16;
    if (e0 >= H) return;

    if (e0 + 16 <= H) {
        const int4* base = reinterpret_cast<const int4*>(nodes + (size_t)e0 * DEG);
        int4 nd[4];
#pragma unroll
        for (int k = 0; k < 4; ++k) nd[k] = base[k * 32 + lane];

        int r0 = (lane & 7) * 4;
        float fl = (float)(31 - r0), fr = (float)r0;

        float v[4];
#pragma unroll
        for (int k = 0; k < 4; ++k) {
            float2 s0 = g_s12[nd[k].x];
            float2 s1 = g_s12[nd[k].y];
            float2 s2 = g_s12[nd[k].z];
            float2 s3 = g_s12[nd[k].w];
            v[k] = s0.x * fl          + s0.y * fr
                 + s1.x * (fl - 1.f)  + s1.y * (fr + 1.f)
                 + s2.x * (fl - 2.f)  + s2.y * (fr + 2.f)
                 + s3.x * (fl - 3.f)  + s3.y * (fr + 3.f);
        }
#pragma unroll
        for (int off = 1; off <= 4; off <<= 1)
#pragma unroll
            for (int k = 0; k < 4; ++k)
                v[k] += __shfl_xor_sync(0xFFFFFFFFu, v[k], off);

        if ((lane & 7) == 0) {
            int sub = lane >> 3;                 // 0..3
#pragma unroll
            for (int k = 0; k < 4; ++k)
                ea_out[e0 + 4 * k + sub] = v[k] * (1.0f / NPAIRS);
        }
    } else {
        for (int i = 0; i < 16; ++i) {
            int e = e0 + i;
            if (e >= H) break;
            int node = nodes[(size_t)e * DEG + lane];
            float2 s = g_s12[node];
            float v = s.x * (float)(DEG - 1 - lane) + s.y * (float)lane;
#pragma unroll
            for (int off = 16; off > 0; off >>= 1)
                v += __shfl_xor_sync(0xFFFFFFFFu, v, off);
            if (lane == 0) ea_out[e] = v * (1.0f / NPAIRS);
        }
    }
}

// ---------------------------------------------------------------------------
extern "C" void kernel_launch(void* const* d_in, const int* in_sizes, int n_in,
                              void* d_out, int out_size)
{
    const float* x    = (const float*)d_in[0];
    const float* W    = (const float*)d_in[1];
    const float* a    = (const float*)d_in[2];
    const int*   hidx = (const int*)d_in[3];

    int N = in_sizes[0] / F_IN;    // 200000
    int E = in_sizes[3] / 2;       // 1,600,000
    int H = E / DEG;               // 50000

    float* h_out  = (float*)d_out;
    float* ea_out = (float*)d_out + (size_t)N * F_OUT;
    const int* nodes = hidx;

    int sms = 0;
    cudaDeviceGetAttribute(&sms, cudaDevAttrMultiProcessorCount, 0);
    if (sms <= 0) sms = 148;

    cudaFuncSetAttribute(gemm_persist_kernel,
                         cudaFuncAttributeMaxDynamicSharedMemorySize, SM_TOTAL);

    int tiles = (N + TILE_M - 1) / TILE_M;    // 1563
    gemm_persist_kernel<<<sms, 256, SM_TOTAL>>>(x, W, a, h_out, N, tiles);

    {
        int warps  = (H + 15) / 16;           // 3125
        int blocks = (warps * 32 + 255) / 256;
        edge_attn_kernel<<<blocks, 256>>>(nodes, ea_out, H);
    }
}